// round 9
// baseline (speedup 1.0000x reference)
#include <cuda_runtime.h>
#include <cstdint>

// C4ByteNibbleVM — integer semantics of the one-hot "neural VM":
//   s = a + b (u32, little-endian ripple carry), out_byte[i] = s_byte[i] ^ a_byte[i],
// output as exact one-hot [B,4,256] f32 (reference softmax is one-hot to ~1e-7).
//
// R7 -> R8: same fetch structure (4-stage x 256B early-exit, one float4 load
// covers two rows: lanes 0-15 row A, lanes 16-31 row B), but the decode moves
// to the idle FMA pipe: index = dot(v, positions+1) via FFMA, f2i (exact for
// one-hot), shift high-half lanes by 16, ONE reduce_add gives both rows'
// (index+1) packed in one u32 (0 = no hit in this chunk).

__global__ __launch_bounds__(256, 6) void c4_vm_kernel(
    const float* __restrict__ a,
    const float* __restrict__ b,
    float* __restrict__ out,
    int nwords)
{
    const int warp = (blockIdx.x * (blockDim.x >> 5)) + (threadIdx.x >> 5);
    const int lane = threadIdx.x & 31;
    if (warp >= nwords) return;

    const int hl = lane >> 4;                   // which row of the pair this lane probes
    const int lr = lane & 15;                   // float4 slot within the 256B chunk
    const int hsh = hl << 4;                    // 0 or 16: packing shift for this lane

    // Position weights (+1 so that 0 means "no hit"): chunk-local index of v.x..v.w
    const float f0 = (float)(lr * 4 + 1);
    const float f1 = f0 + 1.0f, f2 = f0 + 2.0f, f3 = f0 + 3.0f;

    // Row = 64 float4; word block = 4 rows = 256 float4 per side.
    const float4* __restrict__ a4 = reinterpret_cast<const float4*>(a) + (size_t)warp * 256;
    const float4* __restrict__ b4 = reinterpret_cast<const float4*>(b) + (size_t)warp * 256;

    unsigned av = 0, bv = 0;
    unsigned unres = 0xffu;                     // bit gr: row gr (0-3 = a, 4-7 = b) unresolved

#pragma unroll
    for (int s = 0; s < 4; s++) {               // stage s covers floats [s*64, s*64+64) of each row
        if (unres) {                            // warp-uniform
            float4 v[4];
            // ---- 4 paired loads: pair p covers rows {(p&1)*2 + hl} of side p>>1 ----
#pragma unroll
            for (int p = 0; p < 4; p++) {
                const int rp = (p & 1) * 2 + hl;        // row within side (lane-dependent)
                const int gr = (p >> 1) * 4 + rp;       // global row bit
                v[p] = make_float4(0.f, 0.f, 0.f, 0.f);
                if ((unres >> gr) & 1u) {               // per-lane predicate
                    const float4* base = (p < 2) ? a4 : b4;
                    v[p] = __ldcs(base + rp * 64 + s * 16 + lr);
                }
            }
            // ---- decode: FFMA dot + f2i + one packed REDUX per pair ----
#pragma unroll
            for (int p = 0; p < 4; p++) {
                const float4 vv = v[p];
                const float loc =
                    fmaf(vv.x, f0, fmaf(vv.y, f1, fmaf(vv.z, f2, vv.w * f3)));
                const unsigned li = ((unsigned)(int)loc) << hsh;
                const unsigned t = __reduce_add_sync(0xffffffffu, li);
#pragma unroll
                for (int h = 0; h < 2; h++) {
                    const int rp2 = (p & 1) * 2 + h;
                    const int gr2 = (p >> 1) * 4 + rp2;
                    if ((unres >> gr2) & 1u) {          // warp-uniform
                        const unsigned tp = (t >> (16 * h)) & 0xffffu;
                        if (tp) {                       // warp-uniform
                            const unsigned pos = s * 64 + tp - 1;
                            if (p < 2) av |= pos << (8 * rp2);
                            else       bv |= pos << (8 * rp2);
                            unres &= ~(1u << gr2);
                        }
                    }
                }
            }
        }
    }

    // ---- Integer VM op ----
    const unsigned o = (av + bv) ^ av;

    // ---- One-hot output: 4 rows x 1KB, coalesced streaming 128-bit stores ----
    float4* __restrict__ o4 = reinterpret_cast<float4*>(out) + (size_t)warp * 256;

#pragma unroll
    for (int i = 0; i < 4; i++) {
        const unsigned ob = (o >> (8 * i)) & 0xffu;
        const int q = ob >> 2;                  // which float4 (0..63)
        const int e = ob & 3;                   // element within float4
        float4 z0 = make_float4(0.f, 0.f, 0.f, 0.f);
        float4 z1 = make_float4(0.f, 0.f, 0.f, 0.f);
        if (q == lane)      (&z0.x)[e] = 1.0f;
        if (q == lane + 32) (&z1.x)[e] = 1.0f;
        __stcs(&o4[i * 64 + lane], z0);
        __stcs(&o4[i * 64 + 32 + lane], z1);
    }
}

extern "C" void kernel_launch(void* const* d_in, const int* in_sizes, int n_in,
                              void* d_out, int out_size)
{
    const float* a = (const float*)d_in[0];   // a_bytes [B,4,256]
    const float* b = (const float*)d_in[1];   // b_bytes [B,4,256]
    float* out = (float*)d_out;               // [B,4,256]

    const int nwords = in_sizes[0] / 1024;    // B
    const int warps_per_block = 8;            // 256 threads
    const int blocks = (nwords + warps_per_block - 1) / warps_per_block;

    c4_vm_kernel<<<blocks, 256>>>(a, b, out, nwords);
}